// round 13
// baseline (speedup 1.0000x reference)
#include <cuda_runtime.h>
#include <cuda_fp16.h>
#include <math.h>

#define NMAX 50000
#define NPAD 50176
#define EMAX 800000
#define F 64
#define NH 4

// ---------------- scratch (device globals; referenced ONLY from device code) ----------------
__device__ unsigned g_x16[(size_t)NMAX * 32];    // Tx0 fp16, [node][feat/2]
__device__ unsigned g_t116[(size_t)NMAX * 32];   // Tx1 fp16
__device__ unsigned g_t216[(size_t)NMAX * 32];   // Tx2 fp16
__device__ unsigned g_h16[(size_t)NPAD * 32];    // H fp16 (128B rows)
__device__ unsigned g_M16[(size_t)NPAD * 128];   // M fp16, [node][head*32 + feat/2]
__device__ float    g_asrc[NMAX * NH];
__device__ float    g_adst[NMAX * NH];
__device__ float    g_deg[NMAX];
__device__ float    g_dinv[NMAX];
__device__ int      g_cnt[NMAX];
__device__ int      g_loc[NMAX];
__device__ int      g_bsum[256];
__device__ int      g_rowptr[NMAX + 1];
__device__ int      g_slot[EMAX];                // per-edge slot within its dst row
__device__ int2     g_cse[EMAX];                 // CSR: (src, weight-as-int)
__device__ __half   g_wct[64 * 192];             // Cheb weights, transposed [n][3c+j]
__device__ __half   g_wg2[64 * 256];             // 0.25*stacked Wg, [n_out][h*64+c]
__device__ float    g_vs[NH * 64];               // Wg_h^T att_src_h
__device__ float    g_vd[NH * 64];               // Wg_h^T att_dst_h

__device__ __forceinline__ float leaky(float x, float s) {
    return x >= 0.f ? x : s * x;
}

__device__ __forceinline__ void mma16816(float* c, unsigned a0, unsigned a1,
                                         unsigned a2, unsigned a3,
                                         unsigned b0, unsigned b1) {
    asm volatile(
        "mma.sync.aligned.m16n8k16.row.col.f32.f16.f16.f32 "
        "{%0,%1,%2,%3}, {%4,%5,%6,%7}, {%8,%9}, {%0,%1,%2,%3};\n"
        : "+f"(c[0]), "+f"(c[1]), "+f"(c[2]), "+f"(c[3])
        : "r"(a0), "r"(a1), "r"(a2), "r"(a3), "r"(b0), "r"(b1));
}

// ---------------- kernels ----------------
// init counters + one-time weight prep, single launch
__global__ void k_setup(const float* __restrict__ cw, const float* __restrict__ gw,
                        const float* __restrict__ as, const float* __restrict__ ad,
                        int n) {
    int i = blockIdx.x * blockDim.x + threadIdx.x;
    if (i < n) { g_deg[i] = 0.f; g_cnt[i] = 0; }
    if (i < 64 * 192) {
        int nn = i / 192, k = i % 192;
        int c = k / 3, j = k % 3;
        g_wct[i] = __float2half(cw[j * 4096 + c * 64 + nn]);
    } else if (i < 64 * 192 + 64 * 256) {
        int q = i - 64 * 192;
        int nn = q >> 8, k = q & 255;
        int h = k >> 6, c = k & 63;
        g_wg2[q] = __float2half(0.25f * gw[c * 256 + h * 64 + nn]);
    } else if (i < 64 * 192 + 64 * 256 + 512) {
        int q = i - 64 * 192 - 64 * 256;
        int isd = q >> 8, h = (q >> 6) & 3, c = q & 63;
        const float* av = isd ? ad : as;
        float acc = 0.f;
        for (int f = 0; f < 64; f++)
            acc = fmaf(gw[c * 256 + h * 64 + f], av[h * 64 + f], acc);
        if (isd) g_vd[h * 64 + c] = acc; else g_vs[h * 64 + c] = acc;
    }
}

// layernorm (warp/node -> half2) + degree atomics + slot assignment
__global__ void k_lndeg(const float* __restrict__ x, const float* __restrict__ gamma,
                        const float* __restrict__ beta,
                        const int* __restrict__ src, const int* __restrict__ dst,
                        const float* __restrict__ ea, int n, int e, int lnBlocks) {
    if ((int)blockIdx.x < lnBlocks) {
        int warp = (blockIdx.x * blockDim.x + threadIdx.x) >> 5;
        int lane = threadIdx.x & 31;
        if (warp >= n) return;
        float2 v = reinterpret_cast<const float2*>(x)[(size_t)warp * 32 + lane];
        float s = v.x + v.y, sq = v.x * v.x + v.y * v.y;
        #pragma unroll
        for (int o = 16; o; o >>= 1) {
            s  += __shfl_xor_sync(0xffffffffu, s,  o);
            sq += __shfl_xor_sync(0xffffffffu, sq, o);
        }
        float mu  = s * (1.f / 64.f);
        float var = sq * (1.f / 64.f) - mu * mu;
        float r = rsqrtf(var + 1e-5f);
        float2 g2 = reinterpret_cast<const float2*>(gamma)[lane];
        float2 b2 = reinterpret_cast<const float2*>(beta)[lane];
        __half2 h = __floats2half2_rn((v.x - mu) * r * g2.x + b2.x,
                                      (v.y - mu) * r * g2.y + b2.y);
        g_x16[(size_t)warp * 32 + lane] = *(unsigned*)&h;
    } else {
        int i = (blockIdx.x - lnBlocks) * blockDim.x + threadIdx.x;
        if (i >= e) return;
        atomicAdd(&g_deg[src[i]], ea[i]);
        g_slot[i] = atomicAdd(&g_cnt[dst[i]], 1);
    }
}

// scan phase 1: per-block exclusive prefix + block sums; also dinv
__global__ void k_scan1(int n) {
    __shared__ int sm[256];
    int t = threadIdx.x;
    int i = blockIdx.x * 256 + t;
    int v = (i < n) ? g_cnt[i] : 0;
    sm[t] = v;
    __syncthreads();
    for (int o = 1; o < 256; o <<= 1) {
        int u = (t >= o) ? sm[t - o] : 0;
        __syncthreads();
        sm[t] += u;
        __syncthreads();
    }
    if (i < n) {
        g_loc[i] = sm[t] - v;
        float d = g_deg[i];
        g_dinv[i] = d > 0.f ? rsqrtf(d) : 0.f;
    }
    if (t == 255) g_bsum[blockIdx.x] = sm[255];
}

// scan phase 2+3 fused: every block re-scans the (<=256) block sums locally,
// then writes its rowptr slice.
__global__ void k_scan23(int n, int e, int nb) {
    __shared__ int sm[256];
    int t = threadIdx.x;
    int v = (t < nb) ? g_bsum[t] : 0;
    sm[t] = v;
    __syncthreads();
    for (int o = 1; o < 256; o <<= 1) {
        int u = (t >= o) ? sm[t - o] : 0;
        __syncthreads();
        sm[t] += u;
        __syncthreads();
    }
    int boff = (blockIdx.x == 0) ? 0 : sm[blockIdx.x - 1];
    int i = blockIdx.x * 256 + t;
    if (i < n) g_rowptr[i] = boff + g_loc[i];
    if (i == n) g_rowptr[n] = e;
    if (blockIdx.x == 0 && t == 0) g_rowptr[n] = e;   // safe even if n%256==0
}

// place edges into CSR slots without atomics
__global__ void k_fill(const int* __restrict__ src, const int* __restrict__ dst,
                       const float* __restrict__ ea, int e) {
    int i = blockIdx.x * blockDim.x + threadIdx.x;
    if (i >= e) return;
    int s = src[i], d = dst[i];
    int pos = g_rowptr[d] + g_slot[i];
    float w = -(g_dinv[s] * ea[i] * g_dinv[d]);
    g_cse[pos] = make_int2(s, __float_as_int(w));
}

// fp16 gather propagation; warp per node; half2 per lane; 4-edge ILP; fp32 accum
__global__ void k_prop(int n, int phase) {
    int node = (blockIdx.x * blockDim.x + threadIdx.x) >> 5;
    int lane = threadIdx.x & 31;
    if (node >= n) return;
    const unsigned* in = phase ? g_t116 : g_x16;
    int beg = g_rowptr[node], end = g_rowptr[node + 1];
    float2 a0 = {0.f, 0.f}, a1 = {0.f, 0.f}, a2 = {0.f, 0.f}, a3 = {0.f, 0.f};
    int j = beg;
    for (; j + 4 <= end; j += 4) {
        int2 e0 = __ldg(&g_cse[j]),     e1 = __ldg(&g_cse[j + 1]);
        int2 e2 = __ldg(&g_cse[j + 2]), e3 = __ldg(&g_cse[j + 3]);
        unsigned u0 = in[(size_t)e0.x * 32 + lane];
        unsigned u1 = in[(size_t)e1.x * 32 + lane];
        unsigned u2 = in[(size_t)e2.x * 32 + lane];
        unsigned u3 = in[(size_t)e3.x * 32 + lane];
        float2 r0 = __half22float2(*(__half2*)&u0);
        float2 r1 = __half22float2(*(__half2*)&u1);
        float2 r2 = __half22float2(*(__half2*)&u2);
        float2 r3 = __half22float2(*(__half2*)&u3);
        float w0 = __int_as_float(e0.y), w1 = __int_as_float(e1.y);
        float w2 = __int_as_float(e2.y), w3 = __int_as_float(e3.y);
        a0.x = fmaf(w0, r0.x, a0.x); a0.y = fmaf(w0, r0.y, a0.y);
        a1.x = fmaf(w1, r1.x, a1.x); a1.y = fmaf(w1, r1.y, a1.y);
        a2.x = fmaf(w2, r2.x, a2.x); a2.y = fmaf(w2, r2.y, a2.y);
        a3.x = fmaf(w3, r3.x, a3.x); a3.y = fmaf(w3, r3.y, a3.y);
    }
    for (; j < end; j++) {
        int2 e0 = __ldg(&g_cse[j]);
        float w0 = __int_as_float(e0.y);
        unsigned u0 = in[(size_t)e0.x * 32 + lane];
        float2 r0 = __half22float2(*(__half2*)&u0);
        a0.x = fmaf(w0, r0.x, a0.x); a0.y = fmaf(w0, r0.y, a0.y);
    }
    __half2 h = __floats2half2_rn((a0.x + a1.x) + (a2.x + a3.x),
                                  (a0.y + a1.y) + (a2.y + a3.y));
    unsigned* ou = phase ? g_t216 : g_t116;
    ou[(size_t)node * 32 + lane] = *(unsigned*)&h;
}

// tensor-core Cheb GEMM -> H (fp16) + attention dots via vs/vd.
__global__ void __launch_bounds__(256) k_mma1(const float* __restrict__ cb, int n) {
    __shared__ __align__(16) char sbuf[40960];
    __shared__ float s_cb[64];
    __shared__ float s_vs[256], s_vd[256];
    __half* sA     = (__half*)sbuf;              // [128][104]
    unsigned* sW1u = (unsigned*)(sbuf + 26624);  // [64][52] uints

    int t = threadIdx.x;
    int base = blockIdx.x * 128;
    int lane = t & 31, w = t >> 5;
    int g = lane >> 2, tt = lane & 3;

    if (t < 64) s_cb[t] = cb[t];
    s_vs[t] = g_vs[t];
    s_vd[t] = g_vd[t];

    float acc1[8][4];
    #pragma unroll
    for (int i = 0; i < 8; i++)
        #pragma unroll
        for (int q = 0; q < 4; q++) acc1[i][q] = 0.f;

    #pragma unroll
    for (int kh = 0; kh < 2; kh++) {
        __syncthreads();
        #pragma unroll
        for (int i = 0; i < 8; i++) {
            int idx = t + 256 * i;
            int m = idx >> 4, ul = idx & 15;
            int node = base + m;
            unsigned u0 = 0, u1 = 0, u2 = 0;
            if (node < n) {
                size_t off = (size_t)node * 32 + 16 * kh + ul;
                u0 = g_x16[off];
                u1 = g_t116[off];
                u2 = g_t216[off];
            }
            float2 f0 = __half22float2(*(__half2*)&u0);
            float2 f1 = __half22float2(*(__half2*)&u1);
            float2 f2 = __half22float2(*(__half2*)&u2);
            float t2lo = 2.f * f2.x - f0.x, t2hi = 2.f * f2.y - f0.y;
            __half2 p0 = __floats2half2_rn(f0.x, f1.x);
            __half2 p1 = __floats2half2_rn(t2lo, f0.y);
            __half2 p2 = __floats2half2_rn(f1.y, t2hi);
            unsigned* dp = (unsigned*)sA + m * 52 + 3 * ul;
            dp[0] = *(unsigned*)&p0;
            dp[1] = *(unsigned*)&p1;
            dp[2] = *(unsigned*)&p2;
        }
        const unsigned* wct = (const unsigned*)g_wct;   // [64][96] uints
        #pragma unroll
        for (int i = 0; i < 12; i++) {
            int idx = t + 256 * i;
            int nn = idx / 48, c2 = idx % 48;
            sW1u[nn * 52 + c2] = wct[nn * 96 + 48 * kh + c2];
        }
        __syncthreads();
        const unsigned* Au = (const unsigned*)sA;       // [128][52]
        #pragma unroll
        for (int ks = 0; ks < 6; ks++) {
            int arow = 16 * w + g;
            unsigned a0 = Au[arow * 52 + 8 * ks + tt];
            unsigned a1 = Au[(arow + 8) * 52 + 8 * ks + tt];
            unsigned a2 = Au[arow * 52 + 8 * ks + tt + 4];
            unsigned a3 = Au[(arow + 8) * 52 + 8 * ks + tt + 4];
            #pragma unroll
            for (int ns = 0; ns < 8; ns++) {
                int nc = 8 * ns + g;
                unsigned b0 = sW1u[nc * 52 + 8 * ks + tt];
                unsigned b1 = sW1u[nc * 52 + 8 * ks + tt + 4];
                mma16816(acc1[ns], a0, a1, a2, a3, b0, b1);
            }
        }
    }

    int node0 = base + 16 * w + g, node1 = node0 + 8;
    float sv0[NH] = {0,0,0,0}, dv0[NH] = {0,0,0,0};
    float sv1[NH] = {0,0,0,0}, dv1[NH] = {0,0,0,0};
    #pragma unroll
    for (int ns = 0; ns < 8; ns++) {
        int col = 8 * ns + 2 * tt;
        float b0f = s_cb[col], b1f = s_cb[col + 1];
        float h0 = leaky(acc1[ns][0] + b0f, 0.01f);
        float h1 = leaky(acc1[ns][1] + b1f, 0.01f);
        float h2 = leaky(acc1[ns][2] + b0f, 0.01f);
        float h3 = leaky(acc1[ns][3] + b1f, 0.01f);
        if (node0 < n) {
            __half2 hv = __floats2half2_rn(h0, h1);
            g_h16[(size_t)node0 * 32 + (col >> 1)] = *(unsigned*)&hv;
        }
        if (node1 < n) {
            __half2 hv = __floats2half2_rn(h2, h3);
            g_h16[(size_t)node1 * 32 + (col >> 1)] = *(unsigned*)&hv;
        }
        #pragma unroll
        for (int h = 0; h < NH; h++) {
            float vsa = s_vs[h * 64 + col], vsb = s_vs[h * 64 + col + 1];
            float vda = s_vd[h * 64 + col], vdb = s_vd[h * 64 + col + 1];
            sv0[h] = fmaf(h0, vsa, fmaf(h1, vsb, sv0[h]));
            dv0[h] = fmaf(h0, vda, fmaf(h1, vdb, dv0[h]));
            sv1[h] = fmaf(h2, vsa, fmaf(h3, vsb, sv1[h]));
            dv1[h] = fmaf(h2, vda, fmaf(h3, vdb, dv1[h]));
        }
    }
    #pragma unroll
    for (int o = 1; o <= 2; o <<= 1)
        #pragma unroll
        for (int h = 0; h < NH; h++) {
            sv0[h] += __shfl_xor_sync(0xffffffffu, sv0[h], o);
            dv0[h] += __shfl_xor_sync(0xffffffffu, dv0[h], o);
            sv1[h] += __shfl_xor_sync(0xffffffffu, sv1[h], o);
            dv1[h] += __shfl_xor_sync(0xffffffffu, dv1[h], o);
        }
    if (tt == 0) {
        #pragma unroll
        for (int h = 0; h < NH; h++) {
            if (node0 < n) { g_asrc[node0 * 4 + h] = sv0[h]; g_adst[node0 * 4 + h] = dv0[h]; }
            if (node1 < n) { g_asrc[node1 * 4 + h] = sv1[h]; g_adst[node1 * 4 + h] = dv1[h]; }
        }
    }
}

// fused GAT aggregation in H-space
__global__ void k_gat(int n) {
    __shared__ float4 s_ex[8][32];
    __shared__ int    s_s[8][32];
    int wid = threadIdx.x >> 5;
    int node = (blockIdx.x * blockDim.x + threadIdx.x) >> 5;
    int lane = threadIdx.x & 31;
    if (node >= n) return;
    int beg = g_rowptr[node], end = g_rowptr[node + 1];

    const float4* pa = reinterpret_cast<const float4*>(g_asrc);
    const float4* pd = reinterpret_cast<const float4*>(g_adst);
    float4 adv = pd[node];
    float4 asn = pa[node];
    float selfex[NH];
    selfex[0] = __expf(leaky(asn.x + adv.x, 0.2f));
    selfex[1] = __expf(leaky(asn.y + adv.y, 0.2f));
    selfex[2] = __expf(leaky(asn.z + adv.z, 0.2f));
    selfex[3] = __expf(leaky(asn.w + adv.w, 0.2f));

    float2 m[NH];
    {
        unsigned u = g_h16[(size_t)node * 32 + lane];
        float2 f = __half22float2(*(__half2*)&u);
        #pragma unroll
        for (int h = 0; h < NH; h++)
            m[h] = make_float2(selfex[h] * f.x, selfex[h] * f.y);
    }
    float den[NH] = {0.f, 0.f, 0.f, 0.f};

    for (int j0 = beg; j0 < end; j0 += 32) {
        int cnt = min(32, end - j0);
        float4 ex = make_float4(0.f, 0.f, 0.f, 0.f);
        int s = 0;
        if (lane < cnt) {
            s = __ldg(&g_cse[j0 + lane]).x;
            float4 av = pa[s];
            ex.x = __expf(leaky(av.x + adv.x, 0.2f));
            ex.y = __expf(leaky(av.y + adv.y, 0.2f));
            ex.z = __expf(leaky(av.z + adv.z, 0.2f));
            ex.w = __expf(leaky(av.w + adv.w, 0.2f));
            den[0] += ex.x; den[1] += ex.y; den[2] += ex.z; den[3] += ex.w;
        }
        s_ex[wid][lane] = ex;
        s_s[wid][lane] = s;
        __syncwarp();
        #pragma unroll 4
        for (int k = 0; k < cnt; k++) {
            int sk = s_s[wid][k];
            float4 exk = s_ex[wid][k];
            unsigned u = __ldg(&g_h16[(size_t)sk * 32 + lane]);
            float2 f = __half22float2(*(__half2*)&u);
            m[0].x = fmaf(exk.x, f.x, m[0].x); m[0].y = fmaf(exk.x, f.y, m[0].y);
            m[1].x = fmaf(exk.y, f.x, m[1].x); m[1].y = fmaf(exk.y, f.y, m[1].y);
            m[2].x = fmaf(exk.z, f.x, m[2].x); m[2].y = fmaf(exk.z, f.y, m[2].y);
            m[3].x = fmaf(exk.w, f.x, m[3].x); m[3].y = fmaf(exk.w, f.y, m[3].y);
        }
        __syncwarp();
    }

    #pragma unroll
    for (int o = 16; o; o >>= 1)
        #pragma unroll
        for (int h = 0; h < NH; h++)
            den[h] += __shfl_xor_sync(0xffffffffu, den[h], o);

    #pragma unroll
    for (int h = 0; h < NH; h++) {
        float iv = 1.f / (den[h] + selfex[h] + 1e-16f);
        __half2 hv = __floats2half2_rn(m[h].x * iv, m[h].y * iv);
        g_M16[(size_t)node * 128 + h * 32 + lane] = *(unsigned*)&hv;
    }
}

// tensor-core final GEMM: out = leaky(M @ Wg2 + gb). 128 nodes/block.
__global__ void __launch_bounds__(256) k_mma2(const float* __restrict__ gb,
                                              float* __restrict__ out, int n) {
    __shared__ __align__(16) unsigned sB[64 * 132];
    __shared__ float s_gb[64];
    int t = threadIdx.x;
    int lane = t & 31, w = t >> 5;
    int g = lane >> 2, tt = lane & 3;

    const unsigned* wg2u = (const unsigned*)g_wg2;    // [64][128]
    for (int i = t; i < 64 * 128; i += 256) {
        int nc = i >> 7, c2 = i & 127;
        sB[nc * 132 + c2] = wg2u[i];
    }
    if (t < 64) s_gb[t] = gb[t];
    __syncthreads();

    int base = blockIdx.x * 128;
    int arow = 16 * w + g;
    int node0 = base + arow, node1 = node0 + 8;

    float acc[8][4];
    #pragma unroll
    for (int i = 0; i < 8; i++)
        #pragma unroll
        for (int q = 0; q < 4; q++) acc[i][q] = 0.f;

    #pragma unroll
    for (int ks = 0; ks < 16; ks++) {
        unsigned a0 = __ldg(&g_M16[(size_t)node0 * 128 + 8 * ks + tt]);
        unsigned a1 = __ldg(&g_M16[(size_t)node1 * 128 + 8 * ks + tt]);
        unsigned a2 = __ldg(&g_M16[(size_t)node0 * 128 + 8 * ks + tt + 4]);
        unsigned a3 = __ldg(&g_M16[(size_t)node1 * 128 + 8 * ks + tt + 4]);
        #pragma unroll
        for (int ns = 0; ns < 8; ns++) {
            int nc = 8 * ns + g;
            unsigned b0 = sB[nc * 132 + 8 * ks + tt];
            unsigned b1 = sB[nc * 132 + 8 * ks + tt + 4];
            mma16816(acc[ns], a0, a1, a2, a3, b0, b1);
        }
    }

    #pragma unroll
    for (int ns = 0; ns < 8; ns++) {
        int col = 8 * ns + 2 * tt;
        float b0f = s_gb[col], b1f = s_gb[col + 1];
        if (node0 < n) {
            float2 v = make_float2(leaky(acc[ns][0] + b0f, 0.01f),
                                   leaky(acc[ns][1] + b1f, 0.01f));
            *reinterpret_cast<float2*>(out + (size_t)node0 * 64 + col) = v;
        }
        if (node1 < n) {
            float2 v = make_float2(leaky(acc[ns][2] + b0f, 0.01f),
                                   leaky(acc[ns][3] + b1f, 0.01f));
            *reinterpret_cast<float2*>(out + (size_t)node1 * 64 + col) = v;
        }
    }
}

// ---------------- launch ----------------
extern "C" void kernel_launch(void* const* d_in, const int* in_sizes, int n_in,
                              void* d_out, int out_size) {
    const float* x      = (const float*)d_in[0];
    const int*   ei     = (const int*)  d_in[1];
    const float* ea     = (const float*)d_in[2];
    const float* lng    = (const float*)d_in[3];
    const float* lnb    = (const float*)d_in[4];
    const float* cw     = (const float*)d_in[5];
    const float* cb     = (const float*)d_in[6];
    const float* gw     = (const float*)d_in[7];
    const float* as     = (const float*)d_in[8];
    const float* ad     = (const float*)d_in[9];
    const float* gb     = (const float*)d_in[10];
    float* out = (float*)d_out;

    const int n = in_sizes[0] / F;        // 50000
    const int e = in_sizes[2];            // 800000
    const int* src = ei;
    const int* dst = ei + e;

    const int TB = 256;
    auto cdiv = [](long long a, long long b) { return (int)((a + b - 1) / b); };
    int nb = cdiv(n, 256);
    int lnBlocks = cdiv((long long)n * 32, TB);
    int degBlocks = cdiv(e, TB);

    k_setup <<<cdiv(n, TB), TB>>>(cw, gw, as, ad, n);
    k_lndeg <<<lnBlocks + degBlocks, TB>>>(x, lng, lnb, src, dst, ea, n, e, lnBlocks);
    k_scan1 <<<nb, 256>>>(n);
    k_scan23<<<nb, 256>>>(n, e, nb);
    k_fill  <<<cdiv(e, TB), TB>>>(src, dst, ea, e);
    k_prop  <<<cdiv((long long)n * 32, TB), TB>>>(n, 0);
    k_prop  <<<cdiv((long long)n * 32, TB), TB>>>(n, 1);
    k_mma1  <<<cdiv(n, 128), 256>>>(cb, n);
    k_gat   <<<cdiv((long long)n * 32, TB), TB>>>(n);
    k_mma2  <<<cdiv(n, 128), 256>>>(gb, out, n);
}

// round 15
// speedup vs baseline: 1.4140x; 1.4140x over previous
#include <cuda_runtime.h>
#include <cuda_fp16.h>
#include <math.h>

#define NMAX 50000
#define NPAD 50176
#define EMAX 800000
#define F 64
#define NH 4

// ---------------- scratch (device globals; referenced ONLY from device code) ----------------
__device__ unsigned g_x16[(size_t)NMAX * 32];    // Tx0 fp16, [node][feat/2]
__device__ unsigned g_t116[(size_t)NMAX * 32];   // Tx1 fp16
__device__ unsigned g_t216[(size_t)NMAX * 32];   // Tx2 fp16
__device__ unsigned g_h16[(size_t)NPAD * 32];    // H fp16 (128B rows)
__device__ unsigned g_M16[(size_t)NPAD * 128];   // M fp16, [node][head*32 + feat/2]
__device__ float    g_asrc[NMAX * NH];
__device__ float    g_adst[NMAX * NH];
__device__ float    g_deg[NMAX];
__device__ float    g_dinv[NMAX];
__device__ int      g_cnt[NMAX];
__device__ int      g_loc[NMAX];
__device__ int      g_bsum[256];
__device__ int      g_rowptr[NMAX + 1];
__device__ int      g_cursor[NMAX];
__device__ int2     g_cse[EMAX];                 // CSR: (src, weight-as-int)
__device__ __half   g_wct[64 * 192];             // Cheb weights, transposed [n][3c+j]
__device__ __half   g_wg2[64 * 256];             // 0.25*stacked Wg, [n_out][h*64+c]
__device__ float    g_vs[NH * 64];               // Wg_h^T att_src_h
__device__ float    g_vd[NH * 64];               // Wg_h^T att_dst_h

__device__ __forceinline__ float leaky(float x, float s) {
    return x >= 0.f ? x : s * x;
}

__device__ __forceinline__ void mma16816(float* c, unsigned a0, unsigned a1,
                                         unsigned a2, unsigned a3,
                                         unsigned b0, unsigned b1) {
    asm volatile(
        "mma.sync.aligned.m16n8k16.row.col.f32.f16.f16.f32 "
        "{%0,%1,%2,%3}, {%4,%5,%6,%7}, {%8,%9}, {%0,%1,%2,%3};\n"
        : "+f"(c[0]), "+f"(c[1]), "+f"(c[2]), "+f"(c[3])
        : "r"(a0), "r"(a1), "r"(a2), "r"(a3), "r"(b0), "r"(b1));
}

// ---------------- kernels ----------------
// init counters + one-time weight prep, single launch
__global__ void k_setup(const float* __restrict__ cw, const float* __restrict__ gw,
                        const float* __restrict__ as, const float* __restrict__ ad,
                        int n) {
    int i = blockIdx.x * blockDim.x + threadIdx.x;
    if (i < n) { g_deg[i] = 0.f; g_cnt[i] = 0; }
    if (i < 64 * 192) {
        int nn = i / 192, k = i % 192;
        int c = k / 3, j = k % 3;
        g_wct[i] = __float2half(cw[j * 4096 + c * 64 + nn]);
    } else if (i < 64 * 192 + 64 * 256) {
        int q = i - 64 * 192;
        int nn = q >> 8, k = q & 255;
        int h = k >> 6, c = k & 63;
        g_wg2[q] = __float2half(0.25f * gw[c * 256 + h * 64 + nn]);
    } else if (i < 64 * 192 + 64 * 256 + 512) {
        int q = i - 64 * 192 - 64 * 256;
        int isd = q >> 8, h = (q >> 6) & 3, c = q & 63;
        const float* av = isd ? ad : as;
        float acc = 0.f;
        for (int f = 0; f < 64; f++)
            acc = fmaf(gw[c * 256 + h * 64 + f], av[h * 64 + f], acc);
        if (isd) g_vd[h * 64 + c] = acc; else g_vs[h * 64 + c] = acc;
    }
}

// layernorm (warp/node -> half2) + degree/count RED atomics (no return values!)
__global__ void k_lndeg(const float* __restrict__ x, const float* __restrict__ gamma,
                        const float* __restrict__ beta,
                        const int* __restrict__ src, const int* __restrict__ dst,
                        const float* __restrict__ ea, int n, int e, int lnBlocks) {
    if ((int)blockIdx.x < lnBlocks) {
        int warp = (blockIdx.x * blockDim.x + threadIdx.x) >> 5;
        int lane = threadIdx.x & 31;
        if (warp >= n) return;
        float2 v = reinterpret_cast<const float2*>(x)[(size_t)warp * 32 + lane];
        float s = v.x + v.y, sq = v.x * v.x + v.y * v.y;
        #pragma unroll
        for (int o = 16; o; o >>= 1) {
            s  += __shfl_xor_sync(0xffffffffu, s,  o);
            sq += __shfl_xor_sync(0xffffffffu, sq, o);
        }
        float mu  = s * (1.f / 64.f);
        float var = sq * (1.f / 64.f) - mu * mu;
        float r = rsqrtf(var + 1e-5f);
        float2 g2 = reinterpret_cast<const float2*>(gamma)[lane];
        float2 b2 = reinterpret_cast<const float2*>(beta)[lane];
        __half2 h = __floats2half2_rn((v.x - mu) * r * g2.x + b2.x,
                                      (v.y - mu) * r * g2.y + b2.y);
        g_x16[(size_t)warp * 32 + lane] = *(unsigned*)&h;
    } else {
        int i = (blockIdx.x - lnBlocks) * blockDim.x + threadIdx.x;
        if (i >= e) return;
        atomicAdd(&g_deg[src[i]], ea[i]);
        atomicAdd(&g_cnt[dst[i]], 1);
    }
}

// scan phase 1: per-block exclusive prefix + block sums; also dinv
__global__ void k_scan1(int n) {
    __shared__ int sm[256];
    int t = threadIdx.x;
    int i = blockIdx.x * 256 + t;
    int v = (i < n) ? g_cnt[i] : 0;
    sm[t] = v;
    __syncthreads();
    for (int o = 1; o < 256; o <<= 1) {
        int u = (t >= o) ? sm[t - o] : 0;
        __syncthreads();
        sm[t] += u;
        __syncthreads();
    }
    if (i < n) {
        g_loc[i] = sm[t] - v;
        float d = g_deg[i];
        g_dinv[i] = d > 0.f ? rsqrtf(d) : 0.f;
    }
    if (t == 255) g_bsum[blockIdx.x] = sm[255];
}

// scan phase 2+3 fused: every block re-scans the (<=256) block sums locally,
// then writes its rowptr/cursor slice.
__global__ void k_scan23(int n, int e, int nb) {
    __shared__ int sm[256];
    int t = threadIdx.x;
    int v = (t < nb) ? g_bsum[t] : 0;
    sm[t] = v;
    __syncthreads();
    for (int o = 1; o < 256; o <<= 1) {
        int u = (t >= o) ? sm[t - o] : 0;
        __syncthreads();
        sm[t] += u;
        __syncthreads();
    }
    int boff = (blockIdx.x == 0) ? 0 : sm[blockIdx.x - 1];
    int i = blockIdx.x * 256 + t;
    if (i < n) {
        int r = boff + g_loc[i];
        g_rowptr[i] = r;
        g_cursor[i] = r;
    }
    if (blockIdx.x == 0 && t == 0) g_rowptr[n] = e;
}

// place edges into CSR slots (returning atomic isolated here, measured cheap)
__global__ void k_fill(const int* __restrict__ src, const int* __restrict__ dst,
                       const float* __restrict__ ea, int e) {
    int i = blockIdx.x * blockDim.x + threadIdx.x;
    if (i >= e) return;
    int s = src[i], d = dst[i];
    int pos = atomicAdd(&g_cursor[d], 1);
    float w = -(g_dinv[s] * ea[i] * g_dinv[d]);
    g_cse[pos] = make_int2(s, __float_as_int(w));
}

// fp16 gather propagation; warp per node; half2 per lane; 4-edge ILP; fp32 accum
__global__ void k_prop(int n, int phase) {
    int node = (blockIdx.x * blockDim.x + threadIdx.x) >> 5;
    int lane = threadIdx.x & 31;
    if (node >= n) return;
    const unsigned* in = phase ? g_t116 : g_x16;
    int beg = g_rowptr[node], end = g_rowptr[node + 1];
    float2 a0 = {0.f, 0.f}, a1 = {0.f, 0.f}, a2 = {0.f, 0.f}, a3 = {0.f, 0.f};
    int j = beg;
    for (; j + 4 <= end; j += 4) {
        int2 e0 = __ldg(&g_cse[j]),     e1 = __ldg(&g_cse[j + 1]);
        int2 e2 = __ldg(&g_cse[j + 2]), e3 = __ldg(&g_cse[j + 3]);
        unsigned u0 = in[(size_t)e0.x * 32 + lane];
        unsigned u1 = in[(size_t)e1.x * 32 + lane];
        unsigned u2 = in[(size_t)e2.x * 32 + lane];
        unsigned u3 = in[(size_t)e3.x * 32 + lane];
        float2 r0 = __half22float2(*(__half2*)&u0);
        float2 r1 = __half22float2(*(__half2*)&u1);
        float2 r2 = __half22float2(*(__half2*)&u2);
        float2 r3 = __half22float2(*(__half2*)&u3);
        float w0 = __int_as_float(e0.y), w1 = __int_as_float(e1.y);
        float w2 = __int_as_float(e2.y), w3 = __int_as_float(e3.y);
        a0.x = fmaf(w0, r0.x, a0.x); a0.y = fmaf(w0, r0.y, a0.y);
        a1.x = fmaf(w1, r1.x, a1.x); a1.y = fmaf(w1, r1.y, a1.y);
        a2.x = fmaf(w2, r2.x, a2.x); a2.y = fmaf(w2, r2.y, a2.y);
        a3.x = fmaf(w3, r3.x, a3.x); a3.y = fmaf(w3, r3.y, a3.y);
    }
    for (; j < end; j++) {
        int2 e0 = __ldg(&g_cse[j]);
        float w0 = __int_as_float(e0.y);
        unsigned u0 = in[(size_t)e0.x * 32 + lane];
        float2 r0 = __half22float2(*(__half2*)&u0);
        a0.x = fmaf(w0, r0.x, a0.x); a0.y = fmaf(w0, r0.y, a0.y);
    }
    __half2 h = __floats2half2_rn((a0.x + a1.x) + (a2.x + a3.x),
                                  (a0.y + a1.y) + (a2.y + a3.y));
    unsigned* ou = phase ? g_t216 : g_t116;
    ou[(size_t)node * 32 + lane] = *(unsigned*)&h;
}

// tensor-core Cheb GEMM -> H (fp16) + attention dots via vs/vd.
__global__ void __launch_bounds__(256) k_mma1(const float* __restrict__ cb, int n) {
    __shared__ __align__(16) char sbuf[40960];
    __shared__ float s_cb[64];
    __shared__ float s_vs[256], s_vd[256];
    __half* sA     = (__half*)sbuf;              // [128][104]
    unsigned* sW1u = (unsigned*)(sbuf + 26624);  // [64][52] uints

    int t = threadIdx.x;
    int base = blockIdx.x * 128;
    int lane = t & 31, w = t >> 5;
    int g = lane >> 2, tt = lane & 3;

    if (t < 64) s_cb[t] = cb[t];
    s_vs[t] = g_vs[t];
    s_vd[t] = g_vd[t];

    float acc1[8][4];
    #pragma unroll
    for (int i = 0; i < 8; i++)
        #pragma unroll
        for (int q = 0; q < 4; q++) acc1[i][q] = 0.f;

    #pragma unroll
    for (int kh = 0; kh < 2; kh++) {
        __syncthreads();
        #pragma unroll
        for (int i = 0; i < 8; i++) {
            int idx = t + 256 * i;
            int m = idx >> 4, ul = idx & 15;
            int node = base + m;
            unsigned u0 = 0, u1 = 0, u2 = 0;
            if (node < n) {
                size_t off = (size_t)node * 32 + 16 * kh + ul;
                u0 = g_x16[off];
                u1 = g_t116[off];
                u2 = g_t216[off];
            }
            float2 f0 = __half22float2(*(__half2*)&u0);
            float2 f1 = __half22float2(*(__half2*)&u1);
            float2 f2 = __half22float2(*(__half2*)&u2);
            float t2lo = 2.f * f2.x - f0.x, t2hi = 2.f * f2.y - f0.y;
            __half2 p0 = __floats2half2_rn(f0.x, f1.x);
            __half2 p1 = __floats2half2_rn(t2lo, f0.y);
            __half2 p2 = __floats2half2_rn(f1.y, t2hi);
            unsigned* dp = (unsigned*)sA + m * 52 + 3 * ul;
            dp[0] = *(unsigned*)&p0;
            dp[1] = *(unsigned*)&p1;
            dp[2] = *(unsigned*)&p2;
        }
        const unsigned* wct = (const unsigned*)g_wct;   // [64][96] uints
        #pragma unroll
        for (int i = 0; i < 12; i++) {
            int idx = t + 256 * i;
            int nn = idx / 48, c2 = idx % 48;
            sW1u[nn * 52 + c2] = wct[nn * 96 + 48 * kh + c2];
        }
        __syncthreads();
        const unsigned* Au = (const unsigned*)sA;       // [128][52]
        #pragma unroll
        for (int ks = 0; ks < 6; ks++) {
            int arow = 16 * w + g;
            unsigned a0 = Au[arow * 52 + 8 * ks + tt];
            unsigned a1 = Au[(arow + 8) * 52 + 8 * ks + tt];
            unsigned a2 = Au[arow * 52 + 8 * ks + tt + 4];
            unsigned a3 = Au[(arow + 8) * 52 + 8 * ks + tt + 4];
            #pragma unroll
            for (int ns = 0; ns < 8; ns++) {
                int nc = 8 * ns + g;
                unsigned b0 = sW1u[nc * 52 + 8 * ks + tt];
                unsigned b1 = sW1u[nc * 52 + 8 * ks + tt + 4];
                mma16816(acc1[ns], a0, a1, a2, a3, b0, b1);
            }
        }
    }

    int node0 = base + 16 * w + g, node1 = node0 + 8;
    float sv0[NH] = {0,0,0,0}, dv0[NH] = {0,0,0,0};
    float sv1[NH] = {0,0,0,0}, dv1[NH] = {0,0,0,0};
    #pragma unroll
    for (int ns = 0; ns < 8; ns++) {
        int col = 8 * ns + 2 * tt;
        float b0f = s_cb[col], b1f = s_cb[col + 1];
        float h0 = leaky(acc1[ns][0] + b0f, 0.01f);
        float h1 = leaky(acc1[ns][1] + b1f, 0.01f);
        float h2 = leaky(acc1[ns][2] + b0f, 0.01f);
        float h3 = leaky(acc1[ns][3] + b1f, 0.01f);
        if (node0 < n) {
            __half2 hv = __floats2half2_rn(h0, h1);
            g_h16[(size_t)node0 * 32 + (col >> 1)] = *(unsigned*)&hv;
        }
        if (node1 < n) {
            __half2 hv = __floats2half2_rn(h2, h3);
            g_h16[(size_t)node1 * 32 + (col >> 1)] = *(unsigned*)&hv;
        }
        #pragma unroll
        for (int h = 0; h < NH; h++) {
            float vsa = s_vs[h * 64 + col], vsb = s_vs[h * 64 + col + 1];
            float vda = s_vd[h * 64 + col], vdb = s_vd[h * 64 + col + 1];
            sv0[h] = fmaf(h0, vsa, fmaf(h1, vsb, sv0[h]));
            dv0[h] = fmaf(h0, vda, fmaf(h1, vdb, dv0[h]));
            sv1[h] = fmaf(h2, vsa, fmaf(h3, vsb, sv1[h]));
            dv1[h] = fmaf(h2, vda, fmaf(h3, vdb, dv1[h]));
        }
    }
    #pragma unroll
    for (int o = 1; o <= 2; o <<= 1)
        #pragma unroll
        for (int h = 0; h < NH; h++) {
            sv0[h] += __shfl_xor_sync(0xffffffffu, sv0[h], o);
            dv0[h] += __shfl_xor_sync(0xffffffffu, dv0[h], o);
            sv1[h] += __shfl_xor_sync(0xffffffffu, sv1[h], o);
            dv1[h] += __shfl_xor_sync(0xffffffffu, dv1[h], o);
        }
    if (tt == 0) {
        #pragma unroll
        for (int h = 0; h < NH; h++) {
            if (node0 < n) { g_asrc[node0 * 4 + h] = sv0[h]; g_adst[node0 * 4 + h] = dv0[h]; }
            if (node1 < n) { g_asrc[node1 * 4 + h] = sv1[h]; g_adst[node1 * 4 + h] = dv1[h]; }
        }
    }
}

// fused GAT aggregation in H-space
__global__ void k_gat(int n) {
    __shared__ float4 s_ex[8][32];
    __shared__ int    s_s[8][32];
    int wid = threadIdx.x >> 5;
    int node = (blockIdx.x * blockDim.x + threadIdx.x) >> 5;
    int lane = threadIdx.x & 31;
    if (node >= n) return;
    int beg = g_rowptr[node], end = g_rowptr[node + 1];

    const float4* pa = reinterpret_cast<const float4*>(g_asrc);
    const float4* pd = reinterpret_cast<const float4*>(g_adst);
    float4 adv = pd[node];
    float4 asn = pa[node];
    float selfex[NH];
    selfex[0] = __expf(leaky(asn.x + adv.x, 0.2f));
    selfex[1] = __expf(leaky(asn.y + adv.y, 0.2f));
    selfex[2] = __expf(leaky(asn.z + adv.z, 0.2f));
    selfex[3] = __expf(leaky(asn.w + adv.w, 0.2f));

    float2 m[NH];
    {
        unsigned u = g_h16[(size_t)node * 32 + lane];
        float2 f = __half22float2(*(__half2*)&u);
        #pragma unroll
        for (int h = 0; h < NH; h++)
            m[h] = make_float2(selfex[h] * f.x, selfex[h] * f.y);
    }
    float den[NH] = {0.f, 0.f, 0.f, 0.f};

    for (int j0 = beg; j0 < end; j0 += 32) {
        int cnt = min(32, end - j0);
        float4 ex = make_float4(0.f, 0.f, 0.f, 0.f);
        int s = 0;
        if (lane < cnt) {
            s = __ldg(&g_cse[j0 + lane]).x;
            float4 av = pa[s];
            ex.x = __expf(leaky(av.x + adv.x, 0.2f));
            ex.y = __expf(leaky(av.y + adv.y, 0.2f));
            ex.z = __expf(leaky(av.z + adv.z, 0.2f));
            ex.w = __expf(leaky(av.w + adv.w, 0.2f));
            den[0] += ex.x; den[1] += ex.y; den[2] += ex.z; den[3] += ex.w;
        }
        s_ex[wid][lane] = ex;
        s_s[wid][lane] = s;
        __syncwarp();
        #pragma unroll 4
        for (int k = 0; k < cnt; k++) {
            int sk = s_s[wid][k];
            float4 exk = s_ex[wid][k];
            unsigned u = __ldg(&g_h16[(size_t)sk * 32 + lane]);
            float2 f = __half22float2(*(__half2*)&u);
            m[0].x = fmaf(exk.x, f.x, m[0].x); m[0].y = fmaf(exk.x, f.y, m[0].y);
            m[1].x = fmaf(exk.y, f.x, m[1].x); m[1].y = fmaf(exk.y, f.y, m[1].y);
            m[2].x = fmaf(exk.z, f.x, m[2].x); m[2].y = fmaf(exk.z, f.y, m[2].y);
            m[3].x = fmaf(exk.w, f.x, m[3].x); m[3].y = fmaf(exk.w, f.y, m[3].y);
        }
        __syncwarp();
    }

    #pragma unroll
    for (int o = 16; o; o >>= 1)
        #pragma unroll
        for (int h = 0; h < NH; h++)
            den[h] += __shfl_xor_sync(0xffffffffu, den[h], o);

    #pragma unroll
    for (int h = 0; h < NH; h++) {
        float iv = 1.f / (den[h] + selfex[h] + 1e-16f);
        __half2 hv = __floats2half2_rn(m[h].x * iv, m[h].y * iv);
        g_M16[(size_t)node * 128 + h * 32 + lane] = *(unsigned*)&hv;
    }
}

// tensor-core final GEMM: out = leaky(M @ Wg2 + gb). 128 nodes/block.
__global__ void __launch_bounds__(256) k_mma2(const float* __restrict__ gb,
                                              float* __restrict__ out, int n) {
    __shared__ __align__(16) unsigned sB[64 * 132];
    __shared__ float s_gb[64];
    int t = threadIdx.x;
    int lane = t & 31, w = t >> 5;
    int g = lane >> 2, tt = lane & 3;

    const unsigned* wg2u = (const unsigned*)g_wg2;    // [64][128]
    for (int i = t; i < 64 * 128; i += 256) {
        int nc = i >> 7, c2 = i & 127;
        sB[nc * 132 + c2] = wg2u[i];
    }
    if (t < 64) s_gb[t] = gb[t];
    __syncthreads();

    int base = blockIdx.x * 128;
    int arow = 16 * w + g;
    int node0 = base + arow, node1 = node0 + 8;

    float acc[8][4];
    #pragma unroll
    for (int i = 0; i < 8; i++)
        #pragma unroll
        for (int q = 0; q < 4; q++) acc[i][q] = 0.f;

    #pragma unroll
    for (int ks = 0; ks < 16; ks++) {
        unsigned a0 = __ldg(&g_M16[(size_t)node0 * 128 + 8 * ks + tt]);
        unsigned a1 = __ldg(&g_M16[(size_t)node1 * 128 + 8 * ks + tt]);
        unsigned a2 = __ldg(&g_M16[(size_t)node0 * 128 + 8 * ks + tt + 4]);
        unsigned a3 = __ldg(&g_M16[(size_t)node1 * 128 + 8 * ks + tt + 4]);
        #pragma unroll
        for (int ns = 0; ns < 8; ns++) {
            int nc = 8 * ns + g;
            unsigned b0 = sB[nc * 132 + 8 * ks + tt];
            unsigned b1 = sB[nc * 132 + 8 * ks + tt + 4];
            mma16816(acc[ns], a0, a1, a2, a3, b0, b1);
        }
    }

    #pragma unroll
    for (int ns = 0; ns < 8; ns++) {
        int col = 8 * ns + 2 * tt;
        float b0f = s_gb[col], b1f = s_gb[col + 1];
        if (node0 < n) {
            float2 v = make_float2(leaky(acc[ns][0] + b0f, 0.01f),
                                   leaky(acc[ns][1] + b1f, 0.01f));
            *reinterpret_cast<float2*>(out + (size_t)node0 * 64 + col) = v;
        }
        if (node1 < n) {
            float2 v = make_float2(leaky(acc[ns][2] + b0f, 0.01f),
                                   leaky(acc[ns][3] + b1f, 0.01f));
            *reinterpret_cast<float2*>(out + (size_t)node1 * 64 + col) = v;
        }
    }
}

// ---------------- launch ----------------
extern "C" void kernel_launch(void* const* d_in, const int* in_sizes, int n_in,
                              void* d_out, int out_size) {
    const float* x      = (const float*)d_in[0];
    const int*   ei     = (const int*)  d_in[1];
    const float* ea     = (const float*)d_in[2];
    const float* lng    = (const float*)d_in[3];
    const float* lnb    = (const float*)d_in[4];
    const float* cw     = (const float*)d_in[5];
    const float* cb     = (const float*)d_in[6];
    const float* gw     = (const float*)d_in[7];
    const float* as     = (const float*)d_in[8];
    const float* ad     = (const float*)d_in[9];
    const float* gb     = (const float*)d_in[10];
    float* out = (float*)d_out;

    const int n = in_sizes[0] / F;        // 50000
    const int e = in_sizes[2];            // 800000
    const int* src = ei;
    const int* dst = ei + e;

    const int TB = 256;
    auto cdiv = [](long long a, long long b) { return (int)((a + b - 1) / b); };
    int nb = cdiv(n, 256);
    int lnBlocks = cdiv((long long)n * 32, TB);
    int degBlocks = cdiv(e, TB);

    k_setup <<<cdiv(n, TB), TB>>>(cw, gw, as, ad, n);
    k_lndeg <<<lnBlocks + degBlocks, TB>>>(x, lng, lnb, src, dst, ea, n, e, lnBlocks);
    k_scan1 <<<nb, 256>>>(n);
    k_scan23<<<nb, 256>>>(n, e, nb);
    k_fill  <<<cdiv(e, TB), TB>>>(src, dst, ea, e);
    k_prop  <<<cdiv((long long)n * 32, TB), TB>>>(n, 0);
    k_prop  <<<cdiv((long long)n * 32, TB), TB>>>(n, 1);
    k_mma1  <<<cdiv(n, 128), 256>>>(cb, n);
    k_gat   <<<cdiv((long long)n * 32, TB), TB>>>(n);
    k_mma2  <<<cdiv(n, 128), 256>>>(gb, out, n);
}

// round 16
// speedup vs baseline: 1.4785x; 1.0456x over previous
#include <cuda_runtime.h>
#include <cuda_fp16.h>
#include <math.h>

#define NMAX 50000
#define NPAD 50176
#define EMAX 800000
#define F 64
#define NH 4

// ---------------- scratch (device globals; referenced ONLY from device code) ----------------
__device__ unsigned g_x16[(size_t)NMAX * 32];    // Tx0 fp16, [node][feat/2]
__device__ unsigned g_t116[(size_t)NMAX * 32];   // Tx1 fp16
__device__ unsigned g_t216[(size_t)NMAX * 32];   // Tx2 fp16
__device__ unsigned g_h16[(size_t)NPAD * 32];    // H fp16 (128B rows)
__device__ unsigned g_M16[(size_t)NPAD * 128];   // M fp16, [node][head*32 + feat/2]
__device__ float    g_asrc[NMAX * NH];
__device__ float    g_adst[NMAX * NH];
__device__ float    g_deg[NMAX];                 // zero at rest (zeroed by k_scan)
__device__ float    g_dinv[NMAX];
__device__ int      g_cnt[NMAX];                 // zero at rest (zeroed by k_scan)
__device__ int      g_loc[NMAX];
__device__ int      g_bsum[256];
__device__ int      g_scanctr;                   // grid-barrier counter (reset in k_lndeg)
__device__ int      g_rowptr[NMAX + 1];
__device__ int      g_cursor[NMAX];
__device__ int2     g_cse[EMAX];                 // CSR: (src, weight-as-int)
__device__ __half   g_wct[64 * 192];             // Cheb weights, transposed [n][3c+j]
__device__ __half   g_wg2[64 * 256];             // 0.25*stacked Wg, [n_out][h*64+c]
__device__ float    g_vs[NH * 64];               // Wg_h^T att_src_h
__device__ float    g_vd[NH * 64];               // Wg_h^T att_dst_h

__device__ __forceinline__ float leaky(float x, float s) {
    return x >= 0.f ? x : s * x;
}

__device__ __forceinline__ void mma16816(float* c, unsigned a0, unsigned a1,
                                         unsigned a2, unsigned a3,
                                         unsigned b0, unsigned b1) {
    asm volatile(
        "mma.sync.aligned.m16n8k16.row.col.f32.f16.f16.f32 "
        "{%0,%1,%2,%3}, {%4,%5,%6,%7}, {%8,%9}, {%0,%1,%2,%3};\n"
        : "+f"(c[0]), "+f"(c[1]), "+f"(c[2]), "+f"(c[3])
        : "r"(a0), "r"(a1), "r"(a2), "r"(a3), "r"(b0), "r"(b1));
}

// ---------------- kernels ----------------
// layernorm (ln blocks) + degree/count RED atomics (deg blocks) + weight prep (tail blocks)
__global__ void k_lndeg(const float* __restrict__ x, const float* __restrict__ gamma,
                        const float* __restrict__ beta,
                        const int* __restrict__ src, const int* __restrict__ dst,
                        const float* __restrict__ ea,
                        const float* __restrict__ cw, const float* __restrict__ gw,
                        const float* __restrict__ as, const float* __restrict__ ad,
                        int n, int e, int lnBlocks, int degBlocks) {
    if (blockIdx.x == 0 && threadIdx.x == 0) g_scanctr = 0;   // reset grid barrier
    if ((int)blockIdx.x < lnBlocks) {
        int warp = (blockIdx.x * blockDim.x + threadIdx.x) >> 5;
        int lane = threadIdx.x & 31;
        if (warp >= n) return;
        float2 v = reinterpret_cast<const float2*>(x)[(size_t)warp * 32 + lane];
        float s = v.x + v.y, sq = v.x * v.x + v.y * v.y;
        #pragma unroll
        for (int o = 16; o; o >>= 1) {
            s  += __shfl_xor_sync(0xffffffffu, s,  o);
            sq += __shfl_xor_sync(0xffffffffu, sq, o);
        }
        float mu  = s * (1.f / 64.f);
        float var = sq * (1.f / 64.f) - mu * mu;
        float r = rsqrtf(var + 1e-5f);
        float2 g2 = reinterpret_cast<const float2*>(gamma)[lane];
        float2 b2 = reinterpret_cast<const float2*>(beta)[lane];
        __half2 h = __floats2half2_rn((v.x - mu) * r * g2.x + b2.x,
                                      (v.y - mu) * r * g2.y + b2.y);
        g_x16[(size_t)warp * 32 + lane] = *(unsigned*)&h;
    } else if ((int)blockIdx.x < lnBlocks + degBlocks) {
        int i = (blockIdx.x - lnBlocks) * blockDim.x + threadIdx.x;
        if (i >= e) return;
        atomicAdd(&g_deg[src[i]], ea[i]);      // REDG (no return) — keep it that way
        atomicAdd(&g_cnt[dst[i]], 1);          // REDG
    } else {
        int i = (blockIdx.x - lnBlocks - degBlocks) * blockDim.x + threadIdx.x;
        if (i < 64 * 192) {
            int nn = i / 192, k = i % 192;
            int c = k / 3, j = k % 3;
            g_wct[i] = __float2half(cw[j * 4096 + c * 64 + nn]);
        } else if (i < 64 * 192 + 64 * 256) {
            int q = i - 64 * 192;
            int nn = q >> 8, k = q & 255;
            int h = k >> 6, c = k & 63;
            g_wg2[q] = __float2half(0.25f * gw[c * 256 + h * 64 + nn]);
        } else if (i < 64 * 192 + 64 * 256 + 512) {
            int q = i - 64 * 192 - 64 * 256;
            int isd = q >> 8, h = (q >> 6) & 3, c = q & 63;
            const float* av = isd ? ad : as;
            float acc = 0.f;
            for (int f = 0; f < 64; f++)
                acc = fmaf(gw[c * 256 + h * 64 + f], av[h * 64 + f], acc);
            if (isd) g_vd[h * 64 + c] = acc; else g_vs[h * 64 + c] = acc;
        }
    }
}

// single-launch scan with grid barrier. nb blocks (all co-resident, nb<=256).
// phase 1: per-block scan of counts + dinv + zero cnt/deg; publish block sum.
// barrier; phase 2: re-scan block sums locally, write rowptr/cursor slice.
__global__ void k_scan(int n, int e, int nb) {
    __shared__ int sm[256];
    int t = threadIdx.x;
    int i = blockIdx.x * 256 + t;
    int v = (i < n) ? g_cnt[i] : 0;
    sm[t] = v;
    __syncthreads();
    for (int o = 1; o < 256; o <<= 1) {
        int u = (t >= o) ? sm[t - o] : 0;
        __syncthreads();
        sm[t] += u;
        __syncthreads();
    }
    if (i < n) {
        g_loc[i] = sm[t] - v;
        float d = g_deg[i];
        g_dinv[i] = d > 0.f ? rsqrtf(d) : 0.f;
        g_cnt[i] = 0;                          // restore zero-at-rest
        g_deg[i] = 0.f;
    }
    if (t == 0) {
        g_bsum[blockIdx.x] = sm[255];
        __threadfence();
        atomicAdd(&g_scanctr, 1);
        while (atomicAdd(&g_scanctr, 0) < nb) { }   // grid barrier spin
    }
    __syncthreads();
    __threadfence();
    // phase 2: all block sums now visible; volatile read bypasses L1
    int bv = (t < nb) ? ((volatile int*)g_bsum)[t] : 0;
    sm[t] = bv;
    __syncthreads();
    for (int o = 1; o < 256; o <<= 1) {
        int u = (t >= o) ? sm[t - o] : 0;
        __syncthreads();
        sm[t] += u;
        __syncthreads();
    }
    int boff = (blockIdx.x == 0) ? 0 : sm[blockIdx.x - 1];
    if (i < n) {
        int r = boff + g_loc[i];
        g_rowptr[i] = r;
        g_cursor[i] = r;
    }
    if (blockIdx.x == 0 && t == 0) g_rowptr[n] = e;
}

// place edges into CSR slots (returning atomic isolated here, measured cheap)
__global__ void k_fill(const int* __restrict__ src, const int* __restrict__ dst,
                       const float* __restrict__ ea, int e) {
    int i = blockIdx.x * blockDim.x + threadIdx.x;
    if (i >= e) return;
    int s = src[i], d = dst[i];
    int pos = atomicAdd(&g_cursor[d], 1);
    float w = -(g_dinv[s] * ea[i] * g_dinv[d]);
    g_cse[pos] = make_int2(s, __float_as_int(w));
}

// fp16 gather propagation; warp per node; half2 per lane; 8-edge ILP; fp32 accum
__global__ void k_prop(int n, int phase) {
    int node = (blockIdx.x * blockDim.x + threadIdx.x) >> 5;
    int lane = threadIdx.x & 31;
    if (node >= n) return;
    const unsigned* in = phase ? g_t116 : g_x16;
    int beg = g_rowptr[node], end = g_rowptr[node + 1];
    float2 a0 = {0.f, 0.f}, a1 = {0.f, 0.f}, a2 = {0.f, 0.f}, a3 = {0.f, 0.f};
    int j = beg;
    for (; j + 8 <= end; j += 8) {
        int2 e0 = __ldg(&g_cse[j]),     e1 = __ldg(&g_cse[j + 1]);
        int2 e2 = __ldg(&g_cse[j + 2]), e3 = __ldg(&g_cse[j + 3]);
        int2 e4 = __ldg(&g_cse[j + 4]), e5 = __ldg(&g_cse[j + 5]);
        int2 e6 = __ldg(&g_cse[j + 6]), e7 = __ldg(&g_cse[j + 7]);
        unsigned u0 = in[(size_t)e0.x * 32 + lane];
        unsigned u1 = in[(size_t)e1.x * 32 + lane];
        unsigned u2 = in[(size_t)e2.x * 32 + lane];
        unsigned u3 = in[(size_t)e3.x * 32 + lane];
        unsigned u4 = in[(size_t)e4.x * 32 + lane];
        unsigned u5 = in[(size_t)e5.x * 32 + lane];
        unsigned u6 = in[(size_t)e6.x * 32 + lane];
        unsigned u7 = in[(size_t)e7.x * 32 + lane];
        float2 r0 = __half22float2(*(__half2*)&u0);
        float2 r1 = __half22float2(*(__half2*)&u1);
        float2 r2 = __half22float2(*(__half2*)&u2);
        float2 r3 = __half22float2(*(__half2*)&u3);
        float2 r4 = __half22float2(*(__half2*)&u4);
        float2 r5 = __half22float2(*(__half2*)&u5);
        float2 r6 = __half22float2(*(__half2*)&u6);
        float2 r7 = __half22float2(*(__half2*)&u7);
        float w0 = __int_as_float(e0.y), w1 = __int_as_float(e1.y);
        float w2 = __int_as_float(e2.y), w3 = __int_as_float(e3.y);
        float w4 = __int_as_float(e4.y), w5 = __int_as_float(e5.y);
        float w6 = __int_as_float(e6.y), w7 = __int_as_float(e7.y);
        a0.x = fmaf(w0, r0.x, a0.x); a0.y = fmaf(w0, r0.y, a0.y);
        a1.x = fmaf(w1, r1.x, a1.x); a1.y = fmaf(w1, r1.y, a1.y);
        a2.x = fmaf(w2, r2.x, a2.x); a2.y = fmaf(w2, r2.y, a2.y);
        a3.x = fmaf(w3, r3.x, a3.x); a3.y = fmaf(w3, r3.y, a3.y);
        a0.x = fmaf(w4, r4.x, a0.x); a0.y = fmaf(w4, r4.y, a0.y);
        a1.x = fmaf(w5, r5.x, a1.x); a1.y = fmaf(w5, r5.y, a1.y);
        a2.x = fmaf(w6, r6.x, a2.x); a2.y = fmaf(w6, r6.y, a2.y);
        a3.x = fmaf(w7, r7.x, a3.x); a3.y = fmaf(w7, r7.y, a3.y);
    }
    for (; j < end; j++) {
        int2 e0 = __ldg(&g_cse[j]);
        float w0 = __int_as_float(e0.y);
        unsigned u0 = in[(size_t)e0.x * 32 + lane];
        float2 r0 = __half22float2(*(__half2*)&u0);
        a0.x = fmaf(w0, r0.x, a0.x); a0.y = fmaf(w0, r0.y, a0.y);
    }
    __half2 h = __floats2half2_rn((a0.x + a1.x) + (a2.x + a3.x),
                                  (a0.y + a1.y) + (a2.y + a3.y));
    unsigned* ou = phase ? g_t216 : g_t116;
    ou[(size_t)node * 32 + lane] = *(unsigned*)&h;
}

// tensor-core Cheb GEMM -> H (fp16) + attention dots via vs/vd.
__global__ void __launch_bounds__(256) k_mma1(const float* __restrict__ cb, int n) {
    __shared__ __align__(16) char sbuf[40960];
    __shared__ float s_cb[64];
    __shared__ float s_vs[256], s_vd[256];
    __half* sA     = (__half*)sbuf;              // [128][104]
    unsigned* sW1u = (unsigned*)(sbuf + 26624);  // [64][52] uints

    int t = threadIdx.x;
    int base = blockIdx.x * 128;
    int lane = t & 31, w = t >> 5;
    int g = lane >> 2, tt = lane & 3;

    if (t < 64) s_cb[t] = cb[t];
    s_vs[t] = g_vs[t];
    s_vd[t] = g_vd[t];

    float acc1[8][4];
    #pragma unroll
    for (int i = 0; i < 8; i++)
        #pragma unroll
        for (int q = 0; q < 4; q++) acc1[i][q] = 0.f;

    #pragma unroll
    for (int kh = 0; kh < 2; kh++) {
        __syncthreads();
        #pragma unroll
        for (int i = 0; i < 8; i++) {
            int idx = t + 256 * i;
            int m = idx >> 4, ul = idx & 15;
            int node = base + m;
            unsigned u0 = 0, u1 = 0, u2 = 0;
            if (node < n) {
                size_t off = (size_t)node * 32 + 16 * kh + ul;
                u0 = g_x16[off];
                u1 = g_t116[off];
                u2 = g_t216[off];
            }
            float2 f0 = __half22float2(*(__half2*)&u0);
            float2 f1 = __half22float2(*(__half2*)&u1);
            float2 f2 = __half22float2(*(__half2*)&u2);
            float t2lo = 2.f * f2.x - f0.x, t2hi = 2.f * f2.y - f0.y;
            __half2 p0 = __floats2half2_rn(f0.x, f1.x);
            __half2 p1 = __floats2half2_rn(t2lo, f0.y);
            __half2 p2 = __floats2half2_rn(f1.y, t2hi);
            unsigned* dp = (unsigned*)sA + m * 52 + 3 * ul;
            dp[0] = *(unsigned*)&p0;
            dp[1] = *(unsigned*)&p1;
            dp[2] = *(unsigned*)&p2;
        }
        const unsigned* wct = (const unsigned*)g_wct;   // [64][96] uints
        #pragma unroll
        for (int i = 0; i < 12; i++) {
            int idx = t + 256 * i;
            int nn = idx / 48, c2 = idx % 48;
            sW1u[nn * 52 + c2] = wct[nn * 96 + 48 * kh + c2];
        }
        __syncthreads();
        const unsigned* Au = (const unsigned*)sA;       // [128][52]
        #pragma unroll
        for (int ks = 0; ks < 6; ks++) {
            int arow = 16 * w + g;
            unsigned a0 = Au[arow * 52 + 8 * ks + tt];
            unsigned a1 = Au[(arow + 8) * 52 + 8 * ks + tt];
            unsigned a2 = Au[arow * 52 + 8 * ks + tt + 4];
            unsigned a3 = Au[(arow + 8) * 52 + 8 * ks + tt + 4];
            #pragma unroll
            for (int ns = 0; ns < 8; ns++) {
                int nc = 8 * ns + g;
                unsigned b0 = sW1u[nc * 52 + 8 * ks + tt];
                unsigned b1 = sW1u[nc * 52 + 8 * ks + tt + 4];
                mma16816(acc1[ns], a0, a1, a2, a3, b0, b1);
            }
        }
    }

    int node0 = base + 16 * w + g, node1 = node0 + 8;
    float sv0[NH] = {0,0,0,0}, dv0[NH] = {0,0,0,0};
    float sv1[NH] = {0,0,0,0}, dv1[NH] = {0,0,0,0};
    #pragma unroll
    for (int ns = 0; ns < 8; ns++) {
        int col = 8 * ns + 2 * tt;
        float b0f = s_cb[col], b1f = s_cb[col + 1];
        float h0 = leaky(acc1[ns][0] + b0f, 0.01f);
        float h1 = leaky(acc1[ns][1] + b1f, 0.01f);
        float h2 = leaky(acc1[ns][2] + b0f, 0.01f);
        float h3 = leaky(acc1[ns][3] + b1f, 0.01f);
        if (node0 < n) {
            __half2 hv = __floats2half2_rn(h0, h1);
            g_h16[(size_t)node0 * 32 + (col >> 1)] = *(unsigned*)&hv;
        }
        if (node1 < n) {
            __half2 hv = __floats2half2_rn(h2, h3);
            g_h16[(size_t)node1 * 32 + (col >> 1)] = *(unsigned*)&hv;
        }
        #pragma unroll
        for (int h = 0; h < NH; h++) {
            float vsa = s_vs[h * 64 + col], vsb = s_vs[h * 64 + col + 1];
            float vda = s_vd[h * 64 + col], vdb = s_vd[h * 64 + col + 1];
            sv0[h] = fmaf(h0, vsa, fmaf(h1, vsb, sv0[h]));
            dv0[h] = fmaf(h0, vda, fmaf(h1, vdb, dv0[h]));
            sv1[h] = fmaf(h2, vsa, fmaf(h3, vsb, sv1[h]));
            dv1[h] = fmaf(h2, vda, fmaf(h3, vdb, dv1[h]));
        }
    }
    #pragma unroll
    for (int o = 1; o <= 2; o <<= 1)
        #pragma unroll
        for (int h = 0; h < NH; h++) {
            sv0[h] += __shfl_xor_sync(0xffffffffu, sv0[h], o);
            dv0[h] += __shfl_xor_sync(0xffffffffu, dv0[h], o);
            sv1[h] += __shfl_xor_sync(0xffffffffu, sv1[h], o);
            dv1[h] += __shfl_xor_sync(0xffffffffu, dv1[h], o);
        }
    if (tt == 0) {
        #pragma unroll
        for (int h = 0; h < NH; h++) {
            if (node0 < n) { g_asrc[node0 * 4 + h] = sv0[h]; g_adst[node0 * 4 + h] = dv0[h]; }
            if (node1 < n) { g_asrc[node1 * 4 + h] = sv1[h]; g_adst[node1 * 4 + h] = dv1[h]; }
        }
    }
}

// fused GAT aggregation in H-space
__global__ void k_gat(int n) {
    __shared__ float4 s_ex[8][32];
    __shared__ int    s_s[8][32];
    int wid = threadIdx.x >> 5;
    int node = (blockIdx.x * blockDim.x + threadIdx.x) >> 5;
    int lane = threadIdx.x & 31;
    if (node >= n) return;
    int beg = g_rowptr[node], end = g_rowptr[node + 1];

    const float4* pa = reinterpret_cast<const float4*>(g_asrc);
    const float4* pd = reinterpret_cast<const float4*>(g_adst);
    float4 adv = pd[node];
    float4 asn = pa[node];
    float selfex[NH];
    selfex[0] = __expf(leaky(asn.x + adv.x, 0.2f));
    selfex[1] = __expf(leaky(asn.y + adv.y, 0.2f));
    selfex[2] = __expf(leaky(asn.z + adv.z, 0.2f));
    selfex[3] = __expf(leaky(asn.w + adv.w, 0.2f));

    float2 m[NH];
    {
        unsigned u = g_h16[(size_t)node * 32 + lane];
        float2 f = __half22float2(*(__half2*)&u);
        #pragma unroll
        for (int h = 0; h < NH; h++)
            m[h] = make_float2(selfex[h] * f.x, selfex[h] * f.y);
    }
    float den[NH] = {0.f, 0.f, 0.f, 0.f};

    for (int j0 = beg; j0 < end; j0 += 32) {
        int cnt = min(32, end - j0);
        float4 ex = make_float4(0.f, 0.f, 0.f, 0.f);
        int s = 0;
        if (lane < cnt) {
            s = __ldg(&g_cse[j0 + lane]).x;
            float4 av = pa[s];
            ex.x = __expf(leaky(av.x + adv.x, 0.2f));
            ex.y = __expf(leaky(av.y + adv.y, 0.2f));
            ex.z = __expf(leaky(av.z + adv.z, 0.2f));
            ex.w = __expf(leaky(av.w + adv.w, 0.2f));
            den[0] += ex.x; den[1] += ex.y; den[2] += ex.z; den[3] += ex.w;
        }
        s_ex[wid][lane] = ex;
        s_s[wid][lane] = s;
        __syncwarp();
        #pragma unroll 4
        for (int k = 0; k < cnt; k++) {
            int sk = s_s[wid][k];
            float4 exk = s_ex[wid][k];
            unsigned u = __ldg(&g_h16[(size_t)sk * 32 + lane]);
            float2 f = __half22float2(*(__half2*)&u);
            m[0].x = fmaf(exk.x, f.x, m[0].x); m[0].y = fmaf(exk.x, f.y, m[0].y);
            m[1].x = fmaf(exk.y, f.x, m[1].x); m[1].y = fmaf(exk.y, f.y, m[1].y);
            m[2].x = fmaf(exk.z, f.x, m[2].x); m[2].y = fmaf(exk.z, f.y, m[2].y);
            m[3].x = fmaf(exk.w, f.x, m[3].x); m[3].y = fmaf(exk.w, f.y, m[3].y);
        }
        __syncwarp();
    }

    #pragma unroll
    for (int o = 16; o; o >>= 1)
        #pragma unroll
        for (int h = 0; h < NH; h++)
            den[h] += __shfl_xor_sync(0xffffffffu, den[h], o);

    #pragma unroll
    for (int h = 0; h < NH; h++) {
        float iv = 1.f / (den[h] + selfex[h] + 1e-16f);
        __half2 hv = __floats2half2_rn(m[h].x * iv, m[h].y * iv);
        g_M16[(size_t)node * 128 + h * 32 + lane] = *(unsigned*)&hv;
    }
}

// tensor-core final GEMM: out = leaky(M @ Wg2 + gb). 128 nodes/block.
__global__ void __launch_bounds__(256) k_mma2(const float* __restrict__ gb,
                                              float* __restrict__ out, int n) {
    __shared__ __align__(16) unsigned sB[64 * 132];
    __shared__ float s_gb[64];
    int t = threadIdx.x;
    int lane = t & 31, w = t >> 5;
    int g = lane >> 2, tt = lane & 3;

    const unsigned* wg2u = (const unsigned*)g_wg2;    // [64][128]
    for (int i = t; i < 64 * 128; i += 256) {
        int nc = i >> 7, c2 = i & 127;
        sB[nc * 132 + c2] = wg2u[i];
    }
    if (t < 64) s_gb[t] = gb[t];
    __syncthreads();

    int base = blockIdx.x * 128;
    int arow = 16 * w + g;
    int node0 = base + arow, node1 = node0 + 8;

    float acc[8][4];
    #pragma unroll
    for (int i = 0; i < 8; i++)
        #pragma unroll
        for (int q = 0; q < 4; q++) acc[i][q] = 0.f;

    #pragma unroll
    for (int ks = 0; ks < 16; ks++) {
        unsigned a0 = __ldg(&g_M16[(size_t)node0 * 128 + 8 * ks + tt]);
        unsigned a1 = __ldg(&g_M16[(size_t)node1 * 128 + 8 * ks + tt]);
        unsigned a2 = __ldg(&g_M16[(size_t)node0 * 128 + 8 * ks + tt + 4]);
        unsigned a3 = __ldg(&g_M16[(size_t)node1 * 128 + 8 * ks + tt + 4]);
        #pragma unroll
        for (int ns = 0; ns < 8; ns++) {
            int nc = 8 * ns + g;
            unsigned b0 = sB[nc * 132 + 8 * ks + tt];
            unsigned b1 = sB[nc * 132 + 8 * ks + tt + 4];
            mma16816(acc[ns], a0, a1, a2, a3, b0, b1);
        }
    }

    #pragma unroll
    for (int ns = 0; ns < 8; ns++) {
        int col = 8 * ns + 2 * tt;
        float b0f = s_gb[col], b1f = s_gb[col + 1];
        if (node0 < n) {
            float2 v = make_float2(leaky(acc[ns][0] + b0f, 0.01f),
                                   leaky(acc[ns][1] + b1f, 0.01f));
            *reinterpret_cast<float2*>(out + (size_t)node0 * 64 + col) = v;
        }
        if (node1 < n) {
            float2 v = make_float2(leaky(acc[ns][2] + b0f, 0.01f),
                                   leaky(acc[ns][3] + b1f, 0.01f));
            *reinterpret_cast<float2*>(out + (size_t)node1 * 64 + col) = v;
        }
    }
}

// ---------------- launch ----------------
extern "C" void kernel_launch(void* const* d_in, const int* in_sizes, int n_in,
                              void* d_out, int out_size) {
    const float* x      = (const float*)d_in[0];
    const int*   ei     = (const int*)  d_in[1];
    const float* ea     = (const float*)d_in[2];
    const float* lng    = (const float*)d_in[3];
    const float* lnb    = (const float*)d_in[4];
    const float* cw     = (const float*)d_in[5];
    const float* cb     = (const float*)d_in[6];
    const float* gw     = (const float*)d_in[7];
    const float* as     = (const float*)d_in[8];
    const float* ad     = (const float*)d_in[9];
    const float* gb     = (const float*)d_in[10];
    float* out = (float*)d_out;

    const int n = in_sizes[0] / F;        // 50000
    const int e = in_sizes[2];            // 800000
    const int* src = ei;
    const int* dst = ei + e;

    const int TB = 256;
    auto cdiv = [](long long a, long long b) { return (int)((a + b - 1) / b); };
    int nb = cdiv(n, 256);
    int lnBlocks  = cdiv((long long)n * 32, TB);
    int degBlocks = cdiv(e, TB);
    int prepBlocks = cdiv(64 * 192 + 64 * 256 + 512, TB);

    k_lndeg <<<lnBlocks + degBlocks + prepBlocks, TB>>>(
        x, lng, lnb, src, dst, ea, cw, gw, as, ad, n, e, lnBlocks, degBlocks);
    k_scan  <<<nb, 256>>>(n, e, nb);
    k_fill  <<<cdiv(e, TB), TB>>>(src, dst, ea, e);
    k_prop  <<<cdiv((long long)n * 32, TB), TB>>>(n, 0);
    k_prop  <<<cdiv((long long)n * 32, TB), TB>>>(n, 1);
    k_mma1  <<<cdiv(n, 128), 256>>>(cb, n);
    k_gat   <<<cdiv((long long)n * 32, TB), TB>>>(n);
    k_mma2  <<<cdiv(n, 128), 256>>>(gb, out, n);
}